// round 8
// baseline (speedup 1.0000x reference)
#include <cuda_runtime.h>
#include <cstdint>

#define IMAGE_H 200
#define IMAGE_W 200
#define IMG_ELEMS (IMAGE_H * IMAGE_W * 3)   // 120000 floats per image
#define N_PIX (IMAGE_H * IMAGE_W)           // 40000 pixels
#define N_GROUPS (N_PIX / 4)                // 10000 groups of 4 pixels (12 floats)
#define THREADS 512

// One block per image. Build exact per-row column intervals for the two
// Bresenham segments (per-row pixels are contiguous for this both-step
// variant), then procedurally stream the image as float32: no smem image,
// L1 carries only the STG stream + tiny broadcast LDS.
__global__ void __launch_bounds__(THREADS) draw_rope_proc(
    const float* __restrict__ x,          // [M, 6] = (x0,y0,x1,y1,x2,y2)
    const float* __restrict__ resolution, // [2]
    const float* __restrict__ origin,     // [2]
    float* __restrict__ out)              // [M, 200, 200, 3] float32
{
    __shared__ int s_lo[IMAGE_H * 2];  // [row][segment] first line column
    __shared__ int s_hi[IMAGE_H * 2];  // [row][segment] last  line column

    const int m = blockIdx.x;

    // ---- init interval table ----
    for (int i = threadIdx.x; i < IMAGE_H * 2; i += THREADS) {
        s_lo[i] = 0x7fffffff;
        s_hi[i] = -1;
    }

    // ---- rope point pixel indices (all threads, registers) ----
    const float res0 = resolution[0];
    const float res1 = resolution[1];
    const float org0 = origin[0];
    const float org1 = origin[1];
    const float* px = x + (size_t)m * 6;

    int rows[3], cols[3];
#pragma unroll
    for (int i = 0; i < 3; i++) {
        float xf = px[2 * i + 0];
        float yf = px[2 * i + 1];
        rows[i] = (int)floorf(yf / res0 + org0);
        cols[i] = (int)floorf(xf / res1 + org1);
    }

    __syncthreads(); // table initialized

    // ---- build per-row intervals via closed-form Bresenham ----
    // m_k = floor((2*k*minor + major) / (2*major)), pixels k = 0..major inclusive
#pragma unroll
    for (int s = 0; s < 2; s++) {
        const int c0 = cols[s],     r0 = rows[s];
        const int c1 = cols[s + 1], r1 = rows[s + 1];
        const int dx = abs(c1 - c0);
        const int D  = abs(r1 - r0);
        const int sc = (c0 < c1) ? 1 : -1;
        const int sr = (r0 < r1) ? 1 : -1;
        const bool xmajor = (dx >= D);
        const unsigned major = xmajor ? (unsigned)dx : (unsigned)D;
        const unsigned minor = xmajor ? (unsigned)D  : (unsigned)dx;

        if (major == 0u) {
            if (threadIdx.x == 0 &&
                (unsigned)r0 < (unsigned)IMAGE_H && (unsigned)c0 < (unsigned)IMAGE_W) {
                atomicMin(&s_lo[2 * r0 + s], c0);
                atomicMax(&s_hi[2 * r0 + s], c0);
            }
        } else {
            const unsigned den = 2u * major;
            for (unsigned k = threadIdx.x; k <= major; k += THREADS) {
                const int qs = (int)((2u * k * minor + major) / den);
                const int c = xmajor ? (c0 + (int)k * sc) : (c0 + qs * sc);
                const int r = xmajor ? (r0 + qs * sr) : (r0 + (int)k * sr);
                if ((unsigned)r < (unsigned)IMAGE_H && (unsigned)c < (unsigned)IMAGE_W) {
                    atomicMin(&s_lo[2 * r + s], c);
                    atomicMax(&s_hi[2 * r + s], c);
                }
            }
        }
    }

    // markers held in registers; sequential checks reproduce reference
    // overwrite order: line -> red(p0) -> red(p1) -> green(p2)
    const int mk0 = rows[0] * IMAGE_W + cols[0];
    const int mk1 = rows[1] * IMAGE_W + cols[1];
    const int mk2 = rows[2] * IMAGE_W + cols[2];

    __syncthreads(); // intervals complete

    // ---- procedural streaming writeout: 4 pixels (3 float4) per thread-iter ----
    float* img = out + (size_t)m * IMG_ELEMS;
    for (int g = threadIdx.x; g < N_GROUPS; g += THREADS) {
        const int p = g * 4;          // first pixel of group
        int r = p / IMAGE_W;
        int c = p - r * IMAGE_W;

        int lo0 = s_lo[2 * r],     hi0 = s_hi[2 * r];
        int lo1 = s_lo[2 * r + 1], hi1 = s_hi[2 * r + 1];

        float v[12];
#pragma unroll
        for (int u = 0; u < 4; u++) {
            const bool on = (c >= lo0 && c <= hi0) || (c >= lo1 && c <= hi1);
            float vr = on ? 128.f : 0.f, vg = vr, vb = vr;
            const int pp = p + u;
            if (pp == mk0 || pp == mk1) { vr = 255.f; vg = 0.f; vb = 0.f; }
            if (pp == mk2)              { vr = 0.f;   vg = 255.f; vb = 0.f; }
            v[u * 3 + 0] = vr;
            v[u * 3 + 1] = vg;
            v[u * 3 + 2] = vb;
            if (u < 3) {
                c++;
                if (c == IMAGE_W) {   // row wrap inside group
                    c = 0; r++;
                    lo0 = s_lo[2 * r];     hi0 = s_hi[2 * r];
                    lo1 = s_lo[2 * r + 1]; hi1 = s_hi[2 * r + 1];
                }
            }
        }

        float4* o4 = reinterpret_cast<float4*>(img + (size_t)p * 3); // 12-float aligned
        o4[0] = make_float4(v[0], v[1], v[2],  v[3]);
        o4[1] = make_float4(v[4], v[5], v[6],  v[7]);
        o4[2] = make_float4(v[8], v[9], v[10], v[11]);
    }
}

extern "C" void kernel_launch(void* const* d_in, const int* in_sizes, int n_in,
                              void* d_out, int out_size) {
    const float* x          = (const float*)d_in[0]; // [B*T*6] float32
    const float* resolution = (const float*)d_in[1]; // [2]
    const float* origin     = (const float*)d_in[2]; // [2]
    float* out              = (float*)d_out;         // [B,T,200,200,3] float32

    const int M = in_sizes[0] / 6; // B*T = 800 images
    draw_rope_proc<<<M, THREADS>>>(x, resolution, origin, out);
}

// round 9
// speedup vs baseline: 1.1124x; 1.1124x over previous
#include <cuda_runtime.h>
#include <cstdint>

#define IMAGE_H 200
#define IMAGE_W 200
#define ROW_BYTES (IMAGE_W * 3)              // 600
#define IMG_BYTES (IMAGE_H * ROW_BYTES)      // 120000 smem bytes per image
#define IMG_ELEMS IMG_BYTES                  // float elems per output image
#define N16 (IMG_BYTES / 16)                 // 7500 16-byte groups
#define THREADS 512

__device__ __forceinline__ float4 cvt4(uint32_t w) {
    return make_float4((float)( w        & 0xffu),
                       (float)((w >> 8)  & 0xffu),
                       (float)((w >> 16) & 0xffu),
                       (float)( w >> 24        ));
}

// Fused: compose uint8 image in SMEM (zero only the dirty row window +
// closed-form Bresenham + markers), then stream out as float32 with a
// near-instruction-free loop (zero fast path for clean rows).
__global__ void __launch_bounds__(THREADS) draw_rope_fused(
    const float* __restrict__ x,          // [M, 6] = (x0,y0,x1,y1,x2,y2)
    const float* __restrict__ resolution, // [2]
    const float* __restrict__ origin,     // [2]
    float* __restrict__ out)              // [M, 200, 200, 3] float32
{
    extern __shared__ unsigned char s_img[]; // IMG_BYTES

    const int m = blockIdx.x;

    // ---- rope point pixel indices (all threads, registers) ----
    const float res0 = resolution[0];
    const float res1 = resolution[1];
    const float org0 = origin[0];
    const float org1 = origin[1];
    const float* px = x + (size_t)m * 6;

    int rows[3], cols[3];
#pragma unroll
    for (int i = 0; i < 3; i++) {
        float xf = px[2 * i + 0];
        float yf = px[2 * i + 1];
        rows[i] = (int)floorf(yf / res0 + org0);
        cols[i] = (int)floorf(xf / res1 + org1);
    }

    // Dirty row window: segments share p1 and each spans a contiguous row
    // interval, so all drawn pixels lie in [Rmin, Rmax].
    const int Rmin = min(rows[0], min(rows[1], rows[2]));
    const int Rmax = max(rows[0], max(rows[1], rows[2]));

    // ---- Phase 0: zero smem for rows [Rmin-1, Rmax+1] (16B-granular) ----
    {
        const int zlo_row = max(Rmin - 1, 0);
        const int zhi_row = min(Rmax + 2, IMAGE_H);          // exclusive
        const int b_lo = (zlo_row * ROW_BYTES) / 16;         // round down
        const int b_hi = min((zhi_row * ROW_BYTES + 15) / 16, N16); // round up
        uint4 z = make_uint4(0u, 0u, 0u, 0u);
        uint4* s4 = reinterpret_cast<uint4*>(s_img);
        for (int i = b_lo + threadIdx.x; i < b_hi; i += THREADS) s4[i] = z;
    }

    __syncthreads(); // zero window complete

    // ---- Phase 1: closed-form Bresenham into smem ----
    // m_k = floor((2*k*minor + major) / (2*major)), pixels k = 0..major inclusive
#pragma unroll
    for (int s = 0; s < 2; s++) {
        const int c0 = cols[s],     r0 = rows[s];
        const int c1 = cols[s + 1], r1 = rows[s + 1];
        const int dx = abs(c1 - c0);
        const int D  = abs(r1 - r0);
        const int sc = (c0 < c1) ? 1 : -1;
        const int sr = (r0 < r1) ? 1 : -1;
        const bool xmajor = (dx >= D);
        const unsigned major = xmajor ? (unsigned)dx : (unsigned)D;
        const unsigned minor = xmajor ? (unsigned)D  : (unsigned)dx;

        if (major == 0u) {
            if (threadIdx.x == 0 &&
                (unsigned)r0 < (unsigned)IMAGE_H && (unsigned)c0 < (unsigned)IMAGE_W) {
                unsigned char* q = s_img + (r0 * IMAGE_W + c0) * 3;
                q[0] = 128; q[1] = 128; q[2] = 128;
            }
        } else {
            const unsigned den = 2u * major;
            for (unsigned k = threadIdx.x; k <= major; k += THREADS) {
                const int qs = (int)((2u * k * minor + major) / den);
                const int c = xmajor ? (c0 + (int)k * sc) : (c0 + qs * sc);
                const int r = xmajor ? (r0 + qs * sr) : (r0 + (int)k * sr);
                if ((unsigned)r < (unsigned)IMAGE_H && (unsigned)c < (unsigned)IMAGE_W) {
                    unsigned char* q = s_img + (r * IMAGE_W + c) * 3;
                    q[0] = 128; q[1] = 128; q[2] = 128;
                }
            }
        }
    }

    __syncthreads(); // line pixels done before marker overwrites

    // ---- Phase 2: endpoint markers, reference order: red, red, green ----
    if (threadIdx.x == 0) {
        const unsigned char R[3][3] = { {255, 0, 0}, {255, 0, 0}, {0, 255, 0} };
#pragma unroll
        for (int i = 0; i < 3; i++) {
            int r = rows[i], cidx = cols[i];
            if ((unsigned)r < (unsigned)IMAGE_H && (unsigned)cidx < (unsigned)IMAGE_W) {
                unsigned char* q = s_img + (r * IMAGE_W + cidx) * 3;
                q[0] = R[i][0]; q[1] = R[i][1]; q[2] = R[i][2];
            }
        }
    }

    __syncthreads(); // image complete in smem (within dirty window)

    // ---- Phase 3: stream out as float32 ----
    // Each 16B smem group -> 16 floats (4x STG.128). Groups outside the dirty
    // window emit constant zeros (no LDS, no converts). A group spans rows
    // [row_lo, row_lo+1]; margin rows are zeroed so boundary reads are valid.
    {
        const uint4* s4 = reinterpret_cast<const uint4*>(s_img);
        float4* o4 = reinterpret_cast<float4*>(out + (size_t)m * IMG_ELEMS);
        const float4 zf = make_float4(0.f, 0.f, 0.f, 0.f);
        for (int i = threadIdx.x; i < N16; i += THREADS) {
            const int row_lo = (i * 16) / ROW_BYTES;
            if (row_lo + 1 >= Rmin && row_lo <= Rmax) {
                uint4 w = s4[i];
                o4[4 * i + 0] = cvt4(w.x);
                o4[4 * i + 1] = cvt4(w.y);
                o4[4 * i + 2] = cvt4(w.z);
                o4[4 * i + 3] = cvt4(w.w);
            } else {
                o4[4 * i + 0] = zf;
                o4[4 * i + 1] = zf;
                o4[4 * i + 2] = zf;
                o4[4 * i + 3] = zf;
            }
        }
    }
}

extern "C" void kernel_launch(void* const* d_in, const int* in_sizes, int n_in,
                              void* d_out, int out_size) {
    const float* x          = (const float*)d_in[0]; // [B*T*6] float32
    const float* resolution = (const float*)d_in[1]; // [2]
    const float* origin     = (const float*)d_in[2]; // [2]
    float* out              = (float*)d_out;         // [B,T,200,200,3] float32

    const int M = in_sizes[0] / 6; // B*T = 800 images

    cudaFuncSetAttribute(draw_rope_fused,
                         cudaFuncAttributeMaxDynamicSharedMemorySize, IMG_BYTES);
    draw_rope_fused<<<M, THREADS, IMG_BYTES>>>(x, resolution, origin, out);
}

// round 10
// speedup vs baseline: 1.8863x; 1.6956x over previous
#include <cuda_runtime.h>
#include <cstdint>

#define IMAGE_H 200
#define IMAGE_W 200
#define ROW_BYTES (IMAGE_W * 3)              // 600 bytes = 150 u32 per row
#define ROW_U32   (ROW_BYTES / 4)            // 150
#define IMG_BYTES (IMAGE_H * ROW_BYTES)      // 120000 smem bytes per image
#define IMG_ELEMS IMG_BYTES                  // float elems per output image
#define N_U32 (IMG_BYTES / 4)                // 30000 u32 groups (= float4 outputs)
#define THREADS 512

// Fused: compose uint8 image in SMEM (zero only the dirty row window +
// closed-form Bresenham + markers), then stream out as float32 in three
// branch-free loops: zero-prefix / convert-middle (R6 body) / zero-suffix.
__global__ void __launch_bounds__(THREADS) draw_rope_fused(
    const float* __restrict__ x,          // [M, 6] = (x0,y0,x1,y1,x2,y2)
    const float* __restrict__ resolution, // [2]
    const float* __restrict__ origin,     // [2]
    float* __restrict__ out)              // [M, 200, 200, 3] float32
{
    extern __shared__ unsigned char s_img[]; // IMG_BYTES

    const int m = blockIdx.x;

    // ---- rope point pixel indices (all threads, registers) ----
    const float res0 = resolution[0];
    const float res1 = resolution[1];
    const float org0 = origin[0];
    const float org1 = origin[1];
    const float* px = x + (size_t)m * 6;

    int rows[3], cols[3];
#pragma unroll
    for (int i = 0; i < 3; i++) {
        float xf = px[2 * i + 0];
        float yf = px[2 * i + 1];
        rows[i] = (int)floorf(yf / res0 + org0);
        cols[i] = (int)floorf(xf / res1 + org1);
    }

    // Dirty row window (segments share p1; each spans a contiguous row range).
    int Rmin = min(rows[0], min(rows[1], rows[2]));
    int Rmax = max(rows[0], max(rows[1], rows[2]));
    Rmin = max(0, min(Rmin, IMAGE_H - 1));
    Rmax = max(0, min(Rmax, IMAGE_H - 1));

    const int g_lo = Rmin * ROW_U32;          // first dirty u32 group
    const int g_hi = (Rmax + 1) * ROW_U32;    // one past last dirty u32 group

    // ---- Phase 0: zero smem over the dirty window only (STS.128) ----
    {
        const int b_lo = (g_lo * 4) / 16;                 // 16B-aligned down (g_lo*4 % 8 == 0)
        const int b_hi = (g_hi * 4 + 15) / 16;            // 16B-aligned up
        uint4 z = make_uint4(0u, 0u, 0u, 0u);
        uint4* s4 = reinterpret_cast<uint4*>(s_img);
        for (int i = b_lo + threadIdx.x; i < b_hi; i += THREADS) s4[i] = z;
    }

    __syncthreads(); // zero window complete

    // ---- Phase 1: closed-form Bresenham into smem ----
    // m_k = floor((2*k*minor + major) / (2*major)), pixels k = 0..major inclusive
#pragma unroll
    for (int s = 0; s < 2; s++) {
        const int c0 = cols[s],     r0 = rows[s];
        const int c1 = cols[s + 1], r1 = rows[s + 1];
        const int dx = abs(c1 - c0);
        const int D  = abs(r1 - r0);
        const int sc = (c0 < c1) ? 1 : -1;
        const int sr = (r0 < r1) ? 1 : -1;
        const bool xmajor = (dx >= D);
        const unsigned major = xmajor ? (unsigned)dx : (unsigned)D;
        const unsigned minor = xmajor ? (unsigned)D  : (unsigned)dx;

        if (major == 0u) {
            if (threadIdx.x == 0 &&
                (unsigned)r0 < (unsigned)IMAGE_H && (unsigned)c0 < (unsigned)IMAGE_W) {
                unsigned char* q = s_img + (r0 * IMAGE_W + c0) * 3;
                q[0] = 128; q[1] = 128; q[2] = 128;
            }
        } else {
            const unsigned den = 2u * major;
            for (unsigned k = threadIdx.x; k <= major; k += THREADS) {
                const int qs = (int)((2u * k * minor + major) / den);
                const int c = xmajor ? (c0 + (int)k * sc) : (c0 + qs * sc);
                const int r = xmajor ? (r0 + qs * sr) : (r0 + (int)k * sr);
                if ((unsigned)r < (unsigned)IMAGE_H && (unsigned)c < (unsigned)IMAGE_W) {
                    unsigned char* q = s_img + (r * IMAGE_W + c) * 3;
                    q[0] = 128; q[1] = 128; q[2] = 128;
                }
            }
        }
    }

    __syncthreads(); // line pixels done before marker overwrites

    // ---- Phase 2: endpoint markers, reference order: red, red, green ----
    if (threadIdx.x == 0) {
        const unsigned char R[3][3] = { {255, 0, 0}, {255, 0, 0}, {0, 255, 0} };
#pragma unroll
        for (int i = 0; i < 3; i++) {
            int r = rows[i], cidx = cols[i];
            if ((unsigned)r < (unsigned)IMAGE_H && (unsigned)cidx < (unsigned)IMAGE_W) {
                unsigned char* q = s_img + (r * IMAGE_W + cidx) * 3;
                q[0] = R[i][0]; q[1] = R[i][1]; q[2] = R[i][2];
            }
        }
    }

    __syncthreads(); // image complete in smem (within dirty window)

    // ---- Phase 3: stream out as float32, three branch-free loops ----
    {
        const uint32_t* s32 = reinterpret_cast<const uint32_t*>(s_img);
        float4* o4 = reinterpret_cast<float4*>(out + (size_t)m * IMG_ELEMS);
        const float4 zf = make_float4(0.f, 0.f, 0.f, 0.f);

        // zero prefix: rows [0, Rmin)
        for (int i = threadIdx.x; i < g_lo; i += THREADS) o4[i] = zf;

        // dirty middle: rows [Rmin, Rmax] — exact R6 body
        for (int i = g_lo + threadIdx.x; i < g_hi; i += THREADS) {
            uint32_t w = s32[i];
            float4 f;
            f.x = (float)( w        & 0xffu);
            f.y = (float)((w >> 8)  & 0xffu);
            f.z = (float)((w >> 16) & 0xffu);
            f.w = (float)( w >> 24        );
            o4[i] = f;
        }

        // zero suffix: rows (Rmax, IMAGE_H)
        for (int i = g_hi + threadIdx.x; i < N_U32; i += THREADS) o4[i] = zf;
    }
}

extern "C" void kernel_launch(void* const* d_in, const int* in_sizes, int n_in,
                              void* d_out, int out_size) {
    const float* x          = (const float*)d_in[0]; // [B*T*6] float32
    const float* resolution = (const float*)d_in[1]; // [2]
    const float* origin     = (const float*)d_in[2]; // [2]
    float* out              = (float*)d_out;         // [B,T,200,200,3] float32

    const int M = in_sizes[0] / 6; // B*T = 800 images

    cudaFuncSetAttribute(draw_rope_fused,
                         cudaFuncAttributeMaxDynamicSharedMemorySize, IMG_BYTES);
    draw_rope_fused<<<M, THREADS, IMG_BYTES>>>(x, resolution, origin, out);
}

// round 11
// speedup vs baseline: 2.0458x; 1.0845x over previous
#include <cuda_runtime.h>
#include <cstdint>

#define IMAGE_H 200
#define IMAGE_W 200
#define ROW_BYTES (IMAGE_W * 3)              // 600 bytes = 150 u32 per row
#define ROW_U32   (ROW_BYTES / 4)            // 150
#define IMG_BYTES (IMAGE_H * ROW_BYTES)      // 120000 smem bytes per image
#define IMG_ELEMS IMG_BYTES                  // float elems per output image
#define N_U32 (IMG_BYTES / 4)                // 30000 u32 groups (= float4 outputs)
#define THREADS 512

// Fused: hoisted zero prefix/suffix global stores (overlap all prologue),
// compose dirty-window uint8 rows in SMEM via closed-form Bresenham + markers,
// then stream the dirty middle as float32 with the minimal LDS->cvt->STG body.
__global__ void __launch_bounds__(THREADS) draw_rope_fused(
    const float* __restrict__ x,          // [M, 6] = (x0,y0,x1,y1,x2,y2)
    const float* __restrict__ resolution, // [2]
    const float* __restrict__ origin,     // [2]
    float* __restrict__ out)              // [M, 200, 200, 3] float32
{
    extern __shared__ unsigned char s_img[]; // IMG_BYTES

    const int m = blockIdx.x;

    // ---- rope point pixel indices (all threads, registers) ----
    const float res0 = resolution[0];
    const float res1 = resolution[1];
    const float org0 = origin[0];
    const float org1 = origin[1];
    const float* px = x + (size_t)m * 6;

    int rows[3], cols[3];
#pragma unroll
    for (int i = 0; i < 3; i++) {
        float xf = px[2 * i + 0];
        float yf = px[2 * i + 1];
        rows[i] = (int)floorf(yf / res0 + org0);
        cols[i] = (int)floorf(xf / res1 + org1);
    }

    // Dirty row window (segments share p1; each spans a contiguous row range).
    int Rmin = min(rows[0], min(rows[1], rows[2]));
    int Rmax = max(rows[0], max(rows[1], rows[2]));
    Rmin = max(0, min(Rmin, IMAGE_H - 1));
    Rmax = max(0, min(Rmax, IMAGE_H - 1));

    const int g_lo = Rmin * ROW_U32;          // first dirty u32 group
    const int g_hi = (Rmax + 1) * ROW_U32;    // one past last dirty u32 group

    float4* o4 = reinterpret_cast<float4*>(out + (size_t)m * IMG_ELEMS);
    const float4 zf = make_float4(0.f, 0.f, 0.f, 0.f);

    // ---- Phase A (hoisted): zero prefix + suffix of the OUTPUT directly.
    // Depends on nothing; the LSU drains these stores asynchronously while
    // the smem phases below run, keeping the store pipe busy through the
    // prologue and barriers.
    for (int i = threadIdx.x; i < g_lo; i += THREADS) __stcs(&o4[i], zf);
    for (int i = g_hi + threadIdx.x; i < N_U32; i += THREADS) __stcs(&o4[i], zf);

    // ---- Phase 0: zero smem over the dirty window only (STS.128) ----
    {
        const int b_lo = (g_lo * 4) / 16;                 // 16B-aligned down
        const int b_hi = (g_hi * 4 + 15) / 16;            // 16B-aligned up
        uint4 z = make_uint4(0u, 0u, 0u, 0u);
        uint4* s4 = reinterpret_cast<uint4*>(s_img);
        for (int i = b_lo + threadIdx.x; i < b_hi; i += THREADS) s4[i] = z;
    }

    __syncthreads(); // zero window complete

    // ---- Phase 1: closed-form Bresenham into smem ----
    // m_k = floor((2*k*minor + major) / (2*major)), pixels k = 0..major inclusive
#pragma unroll
    for (int s = 0; s < 2; s++) {
        const int c0 = cols[s],     r0 = rows[s];
        const int c1 = cols[s + 1], r1 = rows[s + 1];
        const int dx = abs(c1 - c0);
        const int D  = abs(r1 - r0);
        const int sc = (c0 < c1) ? 1 : -1;
        const int sr = (r0 < r1) ? 1 : -1;
        const bool xmajor = (dx >= D);
        const unsigned major = xmajor ? (unsigned)dx : (unsigned)D;
        const unsigned minor = xmajor ? (unsigned)D  : (unsigned)dx;

        if (major == 0u) {
            if (threadIdx.x == 0 &&
                (unsigned)r0 < (unsigned)IMAGE_H && (unsigned)c0 < (unsigned)IMAGE_W) {
                unsigned char* q = s_img + (r0 * IMAGE_W + c0) * 3;
                q[0] = 128; q[1] = 128; q[2] = 128;
            }
        } else {
            const unsigned den = 2u * major;
            for (unsigned k = threadIdx.x; k <= major; k += THREADS) {
                const int qs = (int)((2u * k * minor + major) / den);
                const int c = xmajor ? (c0 + (int)k * sc) : (c0 + qs * sc);
                const int r = xmajor ? (r0 + qs * sr) : (r0 + (int)k * sr);
                if ((unsigned)r < (unsigned)IMAGE_H && (unsigned)c < (unsigned)IMAGE_W) {
                    unsigned char* q = s_img + (r * IMAGE_W + c) * 3;
                    q[0] = 128; q[1] = 128; q[2] = 128;
                }
            }
        }
    }

    __syncthreads(); // line pixels done before marker overwrites

    // ---- Phase 2: endpoint markers, reference order: red, red, green ----
    if (threadIdx.x == 0) {
        const unsigned char R[3][3] = { {255, 0, 0}, {255, 0, 0}, {0, 255, 0} };
#pragma unroll
        for (int i = 0; i < 3; i++) {
            int r = rows[i], cidx = cols[i];
            if ((unsigned)r < (unsigned)IMAGE_H && (unsigned)cidx < (unsigned)IMAGE_W) {
                unsigned char* q = s_img + (r * IMAGE_W + cidx) * 3;
                q[0] = R[i][0]; q[1] = R[i][1]; q[2] = R[i][2];
            }
        }
    }

    __syncthreads(); // dirty window complete in smem

    // ---- Phase 3: stream dirty middle as float32 (minimal body) ----
    {
        const uint32_t* s32 = reinterpret_cast<const uint32_t*>(s_img);
        for (int i = g_lo + threadIdx.x; i < g_hi; i += THREADS) {
            uint32_t w = s32[i];
            float4 f;
            f.x = (float)( w        & 0xffu);
            f.y = (float)((w >> 8)  & 0xffu);
            f.z = (float)((w >> 16) & 0xffu);
            f.w = (float)( w >> 24        );
            __stcs(&o4[i], f);
        }
    }
}

extern "C" void kernel_launch(void* const* d_in, const int* in_sizes, int n_in,
                              void* d_out, int out_size) {
    const float* x          = (const float*)d_in[0]; // [B*T*6] float32
    const float* resolution = (const float*)d_in[1]; // [2]
    const float* origin     = (const float*)d_in[2]; // [2]
    float* out              = (float*)d_out;         // [B,T,200,200,3] float32

    const int M = in_sizes[0] / 6; // B*T = 800 images

    cudaFuncSetAttribute(draw_rope_fused,
                         cudaFuncAttributeMaxDynamicSharedMemorySize, IMG_BYTES);
    draw_rope_fused<<<M, THREADS, IMG_BYTES>>>(x, resolution, origin, out);
}